// round 2
// baseline (speedup 1.0000x reference)
#include <cuda_runtime.h>
#include <math.h>

#define Nn   262144
#define Ee   2097152
#define Bn   16
#define GXn  22
#define Gn   484
#define Sn   7744
#define EPSn 1e-5f
#define SXn  (16.0f/346.0f)
#define SYn  (12.0f/260.0f)

// ---------------- scratch (device globals; no allocations) ----------------
__device__ float    d_bas [(size_t)Ee*4];
__device__ float    d_bas2[(size_t)Ee*4];
__device__ int      d_deg [Nn];
__device__ int      d_rs  [Nn+1];
__device__ int      d_cur [Nn+1];
__device__ int      d_csr [Ee];
__device__ int      d_bsums[256];
__device__ int      d_cid [Nn];
__device__ int      d_ccnt[Sn];
__device__ float    d_pp  [Sn*2];
__device__ unsigned d_xpe [Sn*32];
__device__ float    d_xp  [Sn*32];
__device__ float    d_wv  [Sn];
__device__ int      d_mark[Bn*Gn*Gn];
__device__ int      d_EcD [1];
__device__ int      d_csrc[Ee];
__device__ int      d_cdst[Ee];
__device__ int      d_degc[Sn];
__device__ int      d_rsc [Sn+1];
__device__ int      d_curc[Sn+1];
__device__ int      d_csrC[Ee];
__device__ unsigned d_mxD [1];
__device__ float    d_T  [(size_t)Nn*128];
__device__ float    d_hP [(size_t)Nn*32];
__device__ float    d_hC [(size_t)Nn*32];
__device__ float    d_scb[(size_t)Nn*32];
__device__ float    d_bnacc[128];
__device__ float    d_ssb[64];
__device__ float    d_twD[1];
__device__ float    d_hc1[Sn*32];
__device__ float    d_hc2[Sn*32];
__device__ float    d_Tc [Sn*128];

// ---------------- helpers ----------------
__device__ __forceinline__ unsigned encf(float f){
    unsigned u = __float_as_uint(f);
    return (u & 0x80000000u) ? ~u : (u | 0x80000000u);
}
__device__ __forceinline__ float decf(unsigned u){
    return (u & 0x80000000u) ? __uint_as_float(u & 0x7FFFFFFFu) : __uint_as_float(~u);
}

// ---------------- prolog ----------------
__global__ void k_zeros(){
    int i = blockIdx.x*blockDim.x + threadIdx.x;
    int st = gridDim.x*blockDim.x;
    for (int j=i; j<Bn*Gn*Gn; j+=st) d_mark[j]=0;
    for (int j=i; j<Nn;       j+=st) d_deg[j]=0;
    for (int j=i; j<Sn;       j+=st){ d_ccnt[j]=0; d_degc[j]=0; }
    for (int j=i; j<Sn*2;     j+=st) d_pp[j]=0.f;
    for (int j=i; j<Sn*32;    j+=st) d_xpe[j]=0u;
    if (i==0){ d_EcD[0]=0; d_mxD[0]=0u; d_twD[0]=0.f; }
}

__global__ void k_prep_edges(const float* __restrict__ ea, const int* __restrict__ dst){
    int e = blockIdx.x*blockDim.x + threadIdx.x;
    if (e >= Ee) return;
    float f0 = fminf(fmaxf(ea[2*(size_t)e  ], 0.f), 1.f);
    float f1 = fminf(fmaxf(ea[2*(size_t)e+1], 0.f), 1.f);
    size_t b = 4*(size_t)e;
    d_bas[b  ] = (1.f-f0)*(1.f-f1);
    d_bas[b+1] = f0*(1.f-f1);
    d_bas[b+2] = (1.f-f0)*f1;
    d_bas[b+3] = f0*f1;
    atomicAdd(&d_deg[dst[e]], 1);
}

__global__ void k_prep_nodes(const float* __restrict__ pos, const int* __restrict__ batch){
    int n = blockIdx.x*blockDim.x + threadIdx.x;
    if (n >= Nn) return;
    float px = pos[2*(size_t)n], py = pos[2*(size_t)n+1];
    int cx = min(max((int)floorf(px / SXn), 0), GXn-1);
    int cy = min(max((int)floorf(py / SYn), 0), GXn-1);
    int cid = batch[n]*Gn + cy*GXn + cx;
    d_cid[n] = cid;
    atomicAdd(&d_ccnt[cid], 1);
    atomicAdd(&d_pp[2*cid],   px);
    atomicAdd(&d_pp[2*cid+1], py);
}

// ---------------- exclusive scan (3 kernels) ----------------
__global__ void k_scan1(const int* __restrict__ in, int* __restrict__ out, int n){
    __shared__ int sh[1024];
    int t = threadIdx.x;
    int base = blockIdx.x*1024;
    int v = (base+t < n) ? in[base+t] : 0;
    sh[t] = v; __syncthreads();
    for (int off=1; off<1024; off<<=1){
        int a = (t>=off) ? sh[t-off] : 0;
        __syncthreads();
        sh[t] += a;
        __syncthreads();
    }
    if (base+t < n) out[base+t] = sh[t]-v;
    if (t==1023) d_bsums[blockIdx.x] = sh[1023];
}
__global__ void k_scan2(int nb){
    __shared__ int sh[256];
    int t = threadIdx.x;
    int v = (t<nb) ? d_bsums[t] : 0;
    sh[t] = v; __syncthreads();
    for (int off=1; off<256; off<<=1){
        int a = (t>=off) ? sh[t-off] : 0;
        __syncthreads();
        sh[t] += a;
        __syncthreads();
    }
    if (t<nb) d_bsums[t] = sh[t]-v;
}
__global__ void k_scan3(const int* __restrict__ in, int* __restrict__ out, int* __restrict__ cur, int n){
    int i = blockIdx.x*blockDim.x + threadIdx.x;
    if (i >= n) return;
    int v = out[i] + d_bsums[i>>10];
    out[i] = v; cur[i] = v;
    if (i == n-1){ int tot = v + in[i]; out[n]=tot; cur[n]=tot; }
}

__global__ void k_scatter(const int* __restrict__ dst){
    int e = blockIdx.x*blockDim.x + threadIdx.x;
    if (e >= Ee) return;
    int p = atomicAdd(&d_cur[dst[e]], 1);
    d_csr[p] = e;
}

// ---------------- node transform: T[n, k*cout+c] = sum_i x[n,i]*W[k,i,c] ----------------
__global__ void k_xform(const float* __restrict__ X, const float* __restrict__ W,
                        float* __restrict__ T, int nrows, int cin, int cout){
    __shared__ float Wsh[32*128];
    int K4 = 4*cout;
    for (int idx=threadIdx.x; idx<cin*K4; idx+=blockDim.x){
        int i = idx / K4, o = idx - i*K4;
        int k = o / cout, c = o - k*cout;
        Wsh[i*K4+o] = W[(k*cin+i)*cout + c];
    }
    __syncthreads();
    int w = threadIdx.x >> 5, lane = threadIdx.x & 31;
    int n = blockIdx.x*(blockDim.x>>5) + w;
    if (n >= nrows) return;
    const float* xr = X + (size_t)n*cin;
    float a0=0.f, a1=0.f, a2=0.f, a3=0.f;
    int nj = K4 >> 5;
    for (int i=0; i<cin; i++){
        float xi = xr[i];
        a0 += xi*Wsh[i*K4+lane];
        if (nj>1) a1 += xi*Wsh[i*K4+lane+32];
        if (nj>2) a2 += xi*Wsh[i*K4+lane+64];
        if (nj>3) a3 += xi*Wsh[i*K4+lane+96];
    }
    float* tr = T + (size_t)n*K4;
    tr[lane] = a0;
    if (nj>1) tr[lane+32] = a1;
    if (nj>2) tr[lane+64] = a2;
    if (nj>3) tr[lane+96] = a3;
}

// ---------------- edge conv: warp per dst, lane = out channel ----------------
__global__ void k_conv(const float* __restrict__ T, const int* __restrict__ csr,
                       const int* __restrict__ rs, const int* __restrict__ srcA,
                       const float* __restrict__ basA, float* __restrict__ hout,
                       int ndst, int cout){
    int gw = (blockIdx.x*blockDim.x + threadIdx.x) >> 5;
    int lane = threadIdx.x & 31;
    if (gw >= ndst) return;
    int beg = rs[gw], end = rs[gw+1];
    float acc = 0.f;
    for (int p=beg; p<end; p++){
        int e = csr[p];
        int s = srcA[e];
        const float* bp = basA + 4*(size_t)e;
        float b0=bp[0], b1=bp[1], b2=bp[2], b3=bp[3];
        const float* tr = T + (size_t)s*(4*cout);
        if (lane < cout)
            acc += b0*tr[lane] + b1*tr[cout+lane] + b2*tr[2*cout+lane] + b3*tr[3*cout+lane];
    }
    if (lane < cout){
        int d = end-beg; if (d < 1) d = 1;
        float v = acc / (float)d;
        v = (v > 0.f) ? v : expm1f(v);
        hout[(size_t)gw*cout + lane] = v;
    }
}

// ---------------- batch norm ----------------
__global__ void k_zerobn(){ if (threadIdx.x < 128) d_bnacc[threadIdx.x] = 0.f; }

__global__ void k_bnred(const float* __restrict__ h, const float* __restrict__ wgt,
                        int n, int cout){
    __shared__ float ss[8][33], sq[8][33];
    int lane = threadIdx.x & 31, w = threadIdx.x >> 5;
    float s=0.f, q=0.f;
    for (int r = blockIdx.x*8 + w; r < n; r += gridDim.x*8){
        float ww = wgt ? wgt[r] : 1.f;
        float v = (lane < cout) ? h[(size_t)r*cout + lane] : 0.f;
        s += ww*v; q += ww*v*v;
    }
    ss[w][lane]=s; sq[w][lane]=q; __syncthreads();
    if (w==0 && lane<cout){
        float S=0.f, Q=0.f;
        #pragma unroll
        for (int j=0;j<8;j++){ S+=ss[j][lane]; Q+=sq[j][lane]; }
        atomicAdd(&d_bnacc[lane],    S);
        atomicAdd(&d_bnacc[64+lane], Q);
    }
}

__global__ void k_bnstats(const float* __restrict__ g, const float* __restrict__ b,
                          int cout, float denom, int useTw){
    int c = threadIdx.x;
    if (c >= cout) return;
    float dn = useTw ? d_twD[0] : denom;
    float m = d_bnacc[c] / dn;
    float v = d_bnacc[64+c] / dn - m*m;
    float sc = g[c] * rsqrtf(v + EPSn);
    d_ssb[c]    = sc;
    d_ssb[32+c] = b[c] - m*sc;
}

__global__ void k_bnapply(const float* __restrict__ hin, float* __restrict__ hout,
                          const float* __restrict__ addsrc, float* __restrict__ cpy,
                          int n, int cout){
    int idx = blockIdx.x*blockDim.x + threadIdx.x;
    if (idx >= n*cout) return;
    int c = idx & (cout-1);
    float v = hin[idx]*d_ssb[c] + d_ssb[32+c];
    if (addsrc) v += addsrc[idx];
    hout[idx] = v;
    if (cpy) cpy[idx] = v;
}

// ---------------- pooling ----------------
__global__ void k_poolmax(const float* __restrict__ h){
    int idx = blockIdx.x*blockDim.x + threadIdx.x;
    if (idx >= Nn*32) return;
    int n = idx >> 5, c = idx & 31;
    atomicMax(&d_xpe[d_cid[n]*32 + c], encf(h[idx]));
}

__global__ void k_cellfin(){
    int idx = blockIdx.x*blockDim.x + threadIdx.x;
    if (idx >= Sn*32) return;
    int s = idx >> 5, c = idx & 31;
    int cnt = d_ccnt[s];
    if (c == 0){
        float inv = 1.f / (float)(cnt > 1 ? cnt : 1);
        d_pp[2*s]   *= inv;
        d_pp[2*s+1] *= inv;
        float w = (cnt > 0) ? 1.f : 0.f;
        d_wv[s] = w;
        if (cnt > 0) atomicAdd(&d_twD[0], 1.f);
    }
    d_xp[idx] = (cnt > 0) ? decf(d_xpe[idx]) : 0.f;
}

__global__ void k_cedges(const int* __restrict__ src, const int* __restrict__ dst){
    int e = blockIdx.x*blockDim.x + threadIdx.x;
    if (e >= Ee) return;
    int cs = d_cid[src[e]], cd = d_cid[dst[e]];
    if (cs == cd) return;
    int b = cs / Gn;
    int ld = cd - b*Gn;
    if ((unsigned)ld >= (unsigned)Gn) return;   // safety (same-batch by construction)
    int key = b*Gn*Gn + (cs - b*Gn)*Gn + ld;
    if (atomicExch(&d_mark[key], 1) == 0){
        int i = atomicAdd(&d_EcD[0], 1);
        d_csrc[i] = cs; d_cdst[i] = cd;
        atomicAdd(&d_degc[cd], 1);
        float cx = d_pp[2*cs]   - d_pp[2*cd];
        float cy = d_pp[2*cs+1] - d_pp[2*cd+1];
        float m = fmaxf(fabsf(cx), fabsf(cy));
        atomicMax(&d_mxD[0], __float_as_uint(m));   // m >= 0: bits monotonic
    }
}

__global__ void k_bas2(){
    int i = blockIdx.x*blockDim.x + threadIdx.x;
    if (i >= d_EcD[0]) return;
    float mx = __uint_as_float(d_mxD[0]);
    float den = 2.f*mx + 1e-12f;
    int cs = d_csrc[i], cd = d_cdst[i];
    float u0 = (d_pp[2*cs]   - d_pp[2*cd])   / den + 0.5f;
    float u1 = (d_pp[2*cs+1] - d_pp[2*cd+1]) / den + 0.5f;
    float f0 = fminf(fmaxf(u0, 0.f), 1.f);
    float f1 = fminf(fmaxf(u1, 0.f), 1.f);
    size_t b = 4*(size_t)i;
    d_bas2[b  ] = (1.f-f0)*(1.f-f1);
    d_bas2[b+1] = f0*(1.f-f1);
    d_bas2[b+2] = (1.f-f0)*f1;
    d_bas2[b+3] = f0*f1;
}

__global__ void k_scatterC(){
    int i = blockIdx.x*blockDim.x + threadIdx.x;
    if (i >= d_EcD[0]) return;
    int p = atomicAdd(&d_curc[d_cdst[i]], 1);
    d_csrC[p] = i;
}

// ---------------- final: per-batch weighted mean + FC ----------------
__global__ void k_final(const float* __restrict__ h, const float* __restrict__ fcW,
                        float* __restrict__ out){
    __shared__ float ss[8][33];
    __shared__ float sw8[8];
    __shared__ float gm[32];
    __shared__ float swv;
    int b = blockIdx.x;
    int lane = threadIdx.x & 31, w = threadIdx.x >> 5;
    float acc = 0.f, accw = 0.f;
    for (int s = b*Gn + w; s < (b+1)*Gn; s += 8){
        float ww = d_wv[s];
        acc += ww * h[(size_t)s*32 + lane];
        accw += ww;
    }
    ss[w][lane] = acc;
    if (lane == 0) sw8[w] = accw;
    __syncthreads();
    if (threadIdx.x < 32){
        float S = 0.f;
        #pragma unroll
        for (int j=0;j<8;j++) S += ss[j][threadIdx.x];
        gm[threadIdx.x] = S;
    }
    if (threadIdx.x == 0){
        float W = 0.f;
        #pragma unroll
        for (int j=0;j<8;j++) W += sw8[j];
        swv = W;
    }
    __syncthreads();
    if (threadIdx.x < 10){
        float o = 0.f;
        #pragma unroll
        for (int c=0;c<32;c++) o += (gm[c]/swv) * fcW[c*10 + threadIdx.x];
        out[b*10 + threadIdx.x] = o;
    }
}

// ---------------- host ----------------
template <typename T>
static T* devptr(const void* sym){
    void* p = nullptr;
    cudaGetSymbolAddress(&p, sym);
    return (T*)p;
}

extern "C" void kernel_launch(void* const* d_in, const int* in_sizes, int n_in,
                              void* d_out, int out_size){
    const float* x     = (const float*)d_in[0];
    const float* pos   = (const float*)d_in[1];
    const int*   batch = (const int*)  d_in[2];
    const int*   ei    = (const int*)  d_in[3];
    const int*   src   = ei;
    const int*   dst   = ei + Ee;
    const float* ea    = (const float*)d_in[4];
    const float* fcW   = (const float*)d_in[29];
    float* out = (float*)d_out;

    float* pT    = devptr<float>(d_T);
    float* phP   = devptr<float>(d_hP);
    float* phC   = devptr<float>(d_hC);
    float* psc   = devptr<float>(d_scb);
    int*   pdeg  = devptr<int>(d_deg);
    int*   prs   = devptr<int>(d_rs);
    int*   pcur  = devptr<int>(d_cur);
    int*   pcsr  = devptr<int>(d_csr);
    int*   pdegc = devptr<int>(d_degc);
    int*   prsc  = devptr<int>(d_rsc);
    int*   pcurc = devptr<int>(d_curc);
    int*   pcsrC = devptr<int>(d_csrC);
    int*   pcsrc = devptr<int>(d_csrc);
    float* pbas  = devptr<float>(d_bas);
    float* pbas2 = devptr<float>(d_bas2);
    float* pxp   = devptr<float>(d_xp);
    float* pwv   = devptr<float>(d_wv);
    float* phc1  = devptr<float>(d_hc1);
    float* phc2  = devptr<float>(d_hc2);
    float* pTc   = devptr<float>(d_Tc);

    // prolog: zero scratch, basis, hist, CSR build
    k_zeros<<<2048,256>>>();
    k_prep_edges<<<Ee/256,256>>>(ea, dst);
    k_prep_nodes<<<Nn/256,256>>>(pos, batch);
    k_scan1<<<256,1024>>>(pdeg, prs, Nn);
    k_scan2<<<1,256>>>(256);
    k_scan3<<<Nn/256,256>>>(pdeg, prs, pcur, Nn);
    k_scatter<<<Ee/256,256>>>(dst);

    // fine layers: W idx, cin, cout, addResidual, copyToSc
    struct Lc { int wi, cin, cout, addsc, cpysc; };
    const Lc L[6] = {
        {5, 10,  8, 0, 0},   // W1
        {8,  8, 16, 0, 0},   // W2
        {11,16, 16, 0, 1},   // W21 -> sc
        {14,16, 16, 0, 0},   // W3
        {17,16, 16, 1, 0},   // W4 + sc
        {20,16, 32, 0, 0},   // W5
    };
    const float* curIn = x;
    for (int l=0; l<6; l++){
        const float* Wl = (const float*)d_in[L[l].wi];
        const float* gl = (const float*)d_in[L[l].wi+1];
        const float* bl = (const float*)d_in[L[l].wi+2];
        int cin = L[l].cin, cout = L[l].cout;
        k_zerobn<<<1,128>>>();
        k_xform<<<Nn/8,256>>>(curIn, Wl, pT, Nn, cin, cout);
        k_conv<<<(Nn*32)/256,256>>>(pT, pcsr, prs, src, pbas, phP, Nn, cout);
        k_bnred<<<2048,256>>>(phP, (const float*)nullptr, Nn, cout);
        k_bnstats<<<1,32>>>(gl, bl, cout, (float)Nn, 0);
        k_bnapply<<<(Nn*cout+255)/256,256>>>(phP, phC,
                                             L[l].addsc ? psc : (const float*)nullptr,
                                             L[l].cpysc ? psc : (float*)nullptr,
                                             Nn, cout);
        curIn = phC;
    }

    // pooling + coarse graph build
    k_poolmax<<<(Nn*32)/256,256>>>(phC);
    k_cellfin<<<(Sn*32+255)/256,256>>>();
    k_cedges<<<Ee/256,256>>>(src, dst);
    k_bas2<<<Ee/256,256>>>();
    k_scan1<<<(Sn+1023)/1024,1024>>>(pdegc, prsc, Sn);
    k_scan2<<<1,256>>>((Sn+1023)/1024);
    k_scan3<<<(Sn+255)/256,256>>>(pdegc, prsc, pcurc, Sn);
    k_scatterC<<<Ee/256,256>>>();

    // coarse layers (weighted BN)
    const float* cIn = pxp;
    const int wis[2] = {23, 26};
    for (int l=0; l<2; l++){
        const float* Wl = (const float*)d_in[wis[l]];
        const float* gl = (const float*)d_in[wis[l]+1];
        const float* bl = (const float*)d_in[wis[l]+2];
        k_zerobn<<<1,128>>>();
        k_xform<<<(Sn+7)/8,256>>>(cIn, Wl, pTc, Sn, 32, 32);
        k_conv<<<(Sn*32)/256,256>>>(pTc, pcsrC, prsc, pcsrc, pbas2, phc1, Sn, 32);
        k_bnred<<<64,256>>>(phc1, pwv, Sn, 32);
        k_bnstats<<<1,32>>>(gl, bl, 32, 0.f, 1);
        k_bnapply<<<(Sn*32+255)/256,256>>>(phc1, phc2,
                                           (const float*)nullptr, (float*)nullptr,
                                           Sn, 32);
        cIn = phc2;
    }

    k_final<<<Bn,256>>>(phc2, fcW, out);
    (void)in_sizes; (void)n_in; (void)out_size;
}

// round 3
// speedup vs baseline: 1.4137x; 1.4137x over previous
#include <cuda_runtime.h>
#include <math.h>

#define Nn   262144
#define Ee   2097152
#define Bn   16
#define GXn  22
#define Gn   484
#define Sn   7744
#define EPSn 1e-5f
#define SXn  (16.0f/346.0f)
#define SYn  (12.0f/260.0f)
#define NCPY 256

// ---------------- scratch (device globals; no allocations) ----------------
__device__ int      d_deg [Nn];
__device__ int      d_rs  [Nn+1];
__device__ int      d_cur [Nn+1];
__device__ int      d_esrcP[Ee];
__device__ float4   d_basP [Ee];
__device__ int      d_bsums[256];
__device__ int      d_cid [Nn];
__device__ int      d_ccnt[Sn];
__device__ float    d_pp  [Sn*2];
__device__ unsigned d_xpe [Sn*32];
__device__ float    d_xp  [Sn*32];
__device__ float    d_wv  [Sn];
__device__ int      d_mark[Bn*Gn*Gn];
__device__ int      d_EcD [1];
__device__ int      d_csrc[Ee];
__device__ int      d_cdst[Ee];
__device__ int      d_degc[Sn];
__device__ int      d_rsc [Sn+1];
__device__ int      d_curc[Sn+1];
__device__ int      d_csrcP[Ee];
__device__ float4   d_bas2P[Ee];
__device__ unsigned d_mxD [1];
__device__ float    d_twD [1];
__device__ float    d_T  [(size_t)Nn*128];
__device__ float    d_U0 [(size_t)Nn*32];
__device__ float    d_U1 [(size_t)Nn*32];
__device__ float    d_U2 [(size_t)Nn*32];
__device__ float    d_C0 [Sn*32];
__device__ float    d_C1 [Sn*32];
__device__ float    d_Tc [Sn*128];
__device__ float    d_bnaccM[8][NCPY][128];
__device__ float    d_ssbL[8][64];

// ---------------- helpers ----------------
__device__ __forceinline__ unsigned encf(float f){
    unsigned u = __float_as_uint(f);
    return (u & 0x80000000u) ? ~u : (u | 0x80000000u);
}
__device__ __forceinline__ float decf(unsigned u){
    return (u & 0x80000000u) ? __uint_as_float(u & 0x7FFFFFFFu) : __uint_as_float(~u);
}

// ---------------- prolog ----------------
__global__ void k_zeros(){
    int i = blockIdx.x*blockDim.x + threadIdx.x;
    int st = gridDim.x*blockDim.x;
    for (int j=i; j<Bn*Gn*Gn; j+=st) d_mark[j]=0;
    for (int j=i; j<Nn;       j+=st) d_deg[j]=0;
    for (int j=i; j<Sn;       j+=st){ d_ccnt[j]=0; d_degc[j]=0; }
    for (int j=i; j<Sn*2;     j+=st) d_pp[j]=0.f;
    for (int j=i; j<Sn*32;    j+=st) d_xpe[j]=0u;
    float* bm = &d_bnaccM[0][0][0];
    for (int j=i; j<8*NCPY*128; j+=st) bm[j]=0.f;
    if (i==0){ d_EcD[0]=0; d_mxD[0]=0u; d_twD[0]=0.f; }
}

__global__ void k_hist(const int* __restrict__ dst){
    int e = blockIdx.x*blockDim.x + threadIdx.x;
    if (e >= Ee) return;
    atomicAdd(&d_deg[dst[e]], 1);
}

__global__ void k_prep_nodes(const float* __restrict__ pos, const int* __restrict__ batch){
    int n = blockIdx.x*blockDim.x + threadIdx.x;
    if (n >= Nn) return;
    float px = pos[2*(size_t)n], py = pos[2*(size_t)n+1];
    int cx = min(max((int)floorf(px / SXn), 0), GXn-1);
    int cy = min(max((int)floorf(py / SYn), 0), GXn-1);
    int cid = batch[n]*Gn + cy*GXn + cx;
    d_cid[n] = cid;
    atomicAdd(&d_ccnt[cid], 1);
    atomicAdd(&d_pp[2*cid],   px);
    atomicAdd(&d_pp[2*cid+1], py);
}

// ---------------- exclusive scan (3 kernels) ----------------
__global__ void k_scan1(const int* __restrict__ in, int* __restrict__ out, int n){
    __shared__ int sh[1024];
    int t = threadIdx.x;
    int base = blockIdx.x*1024;
    int v = (base+t < n) ? in[base+t] : 0;
    sh[t] = v; __syncthreads();
    for (int off=1; off<1024; off<<=1){
        int a = (t>=off) ? sh[t-off] : 0;
        __syncthreads();
        sh[t] += a;
        __syncthreads();
    }
    if (base+t < n) out[base+t] = sh[t]-v;
    if (t==1023) d_bsums[blockIdx.x] = sh[1023];
}
__global__ void k_scan2(int nb){
    __shared__ int sh[256];
    int t = threadIdx.x;
    int v = (t<nb) ? d_bsums[t] : 0;
    sh[t] = v; __syncthreads();
    for (int off=1; off<256; off<<=1){
        int a = (t>=off) ? sh[t-off] : 0;
        __syncthreads();
        sh[t] += a;
        __syncthreads();
    }
    if (t<nb) d_bsums[t] = sh[t]-v;
}
__global__ void k_scan3(const int* __restrict__ in, int* __restrict__ out, int* __restrict__ cur, int n){
    int i = blockIdx.x*blockDim.x + threadIdx.x;
    if (i >= n) return;
    int v = out[i] + d_bsums[i>>10];
    out[i] = v; cur[i] = v;
    if (i == n-1){ int tot = v + in[i]; out[n]=tot; cur[n]=tot; }
}

// scatter edges into CSR order, storing src + basis weights directly
__global__ void k_scatter(const int* __restrict__ src, const int* __restrict__ dst,
                          const float* __restrict__ ea){
    int e = blockIdx.x*blockDim.x + threadIdx.x;
    if (e >= Ee) return;
    float f0 = fminf(fmaxf(ea[2*(size_t)e  ], 0.f), 1.f);
    float f1 = fminf(fmaxf(ea[2*(size_t)e+1], 0.f), 1.f);
    int p = atomicAdd(&d_cur[dst[e]], 1);
    d_esrcP[p] = src[e];
    d_basP[p]  = make_float4((1.f-f0)*(1.f-f1), f0*(1.f-f1), (1.f-f0)*f1, f0*f1);
}

// ---------------- node transform with BN fold ----------------
// T[n, k*cout+c] = sum_i (a1_i*X1[n,i] + a2_i*X2[n,i] + (b1_i+b2_i)) * W[k,i,c]
template<int NJ>
__global__ void k_xform(const float* __restrict__ X1, const float* __restrict__ X2,
                        const float* __restrict__ W, float* __restrict__ T,
                        int nrows, int cin, int cout, int ab1, int ab2){
    constexpr int K4 = NJ*32;
    __shared__ float Wsh[32*128];
    __shared__ float A1[32], B1[32], A2[32], B2[32];
    __shared__ float CB[128];
    for (int idx = threadIdx.x; idx < cin*K4; idx += blockDim.x){
        int i = idx / K4, o = idx - i*K4;
        int k = o / cout, cc = o - k*cout;
        Wsh[idx] = W[(k*cin+i)*cout + cc];
    }
    if (threadIdx.x < 32){
        int i = threadIdx.x;
        A1[i] = (ab1 >= 0) ? d_ssbL[ab1][i]    : 1.f;
        B1[i] = (ab1 >= 0) ? d_ssbL[ab1][32+i] : 0.f;
        A2[i] = (ab2 >= 0) ? d_ssbL[ab2][i]    : 0.f;
        B2[i] = (ab2 >= 0) ? d_ssbL[ab2][32+i] : 0.f;
    }
    __syncthreads();
    for (int o = threadIdx.x; o < K4; o += blockDim.x){
        float s = 0.f;
        for (int i = 0; i < cin; i++) s += (B1[i]+B2[i])*Wsh[i*K4+o];
        CB[o] = s;
    }
    __syncthreads();
    int w = threadIdx.x >> 5, lane = threadIdx.x & 31;
    int n = blockIdx.x*8 + w;
    if (n >= nrows) return;
    const float* x1 = X1 + (size_t)n*cin;
    const float* x2 = X2 ? (X2 + (size_t)n*cin) : nullptr;
    float a[NJ];
    #pragma unroll
    for (int j=0;j<NJ;j++) a[j] = CB[lane+32*j];
    for (int i=0;i<cin;i++){
        float xi = A1[i]*x1[i];
        if (x2) xi += A2[i]*x2[i];
        #pragma unroll
        for (int j=0;j<NJ;j++) a[j] += xi*Wsh[i*K4+lane+32*j];
    }
    float* tr = T + (size_t)n*K4;
    #pragma unroll
    for (int j=0;j<NJ;j++) tr[lane+32*j] = a[j];
}

// ---------------- fine conv: 32/COUT dst per warp, fused BN reduce ----------------
template<int COUT>
__global__ void k_convF(const float* __restrict__ T, const int* __restrict__ rs,
                        const int* __restrict__ esrcP, const float4* __restrict__ basP,
                        float* __restrict__ uout, int layer, int ndst){
    constexpr int LC = 32/COUT;
    int lane = threadIdx.x & 31, w = threadIdx.x >> 5;
    int c = lane & (COUT-1);
    int sub = lane / COUT;
    int gw = blockIdx.x*8 + w;
    int d0 = gw*LC + sub;
    float acc = 0.f; int beg = 0, end = 0;
    if (d0 < ndst){ beg = rs[d0]; end = rs[d0+1]; }
    for (int p = beg; p < end; p++){
        int s = esrcP[p];
        float4 b = basP[p];
        const float* tr = T + (size_t)s*(4*COUT);
        acc += b.x*tr[c] + b.y*tr[COUT+c] + b.z*tr[2*COUT+c] + b.w*tr[3*COUT+c];
    }
    float v = 0.f;
    if (d0 < ndst){
        int dg = end - beg; if (dg < 1) dg = 1;
        v = acc / (float)dg;
        v = (v > 0.f) ? v : expm1f(v);
        uout[(size_t)d0*COUT + c] = v;
    }
    __shared__ float ss[8][33], sq[8][33];
    ss[w][lane] = v; sq[w][lane] = v*v;
    __syncthreads();
    if (w == 0 && lane < COUT){
        float S = 0.f, Q = 0.f;
        #pragma unroll
        for (int j=0;j<8;j++){
            #pragma unroll
            for (int t=0;t<LC;t++){ S += ss[j][lane + t*COUT]; Q += sq[j][lane + t*COUT]; }
        }
        int cp = blockIdx.x & (NCPY-1);
        atomicAdd(&d_bnaccM[layer][cp][lane],    S);
        atomicAdd(&d_bnaccM[layer][cp][64+lane], Q);
    }
}

// ---------------- coarse conv: block per dst (high degree), weighted BN reduce --------
__global__ void k_convC(const float* __restrict__ T, const int* __restrict__ rs,
                        const int* __restrict__ esrcP, const float4* __restrict__ basP,
                        float* __restrict__ uout, int layer){
    int d0 = blockIdx.x;
    int lane = threadIdx.x & 31, w = threadIdx.x >> 5;
    int beg = rs[d0], end = rs[d0+1];
    float acc = 0.f;
    for (int p = beg + w; p < end; p += 8){
        int s = esrcP[p];
        float4 b = basP[p];
        const float* tr = T + (size_t)s*128;
        acc += b.x*tr[lane] + b.y*tr[32+lane] + b.z*tr[64+lane] + b.w*tr[96+lane];
    }
    __shared__ float ss[8][33];
    ss[w][lane] = acc; __syncthreads();
    if (w == 0){
        float S = 0.f;
        #pragma unroll
        for (int j=0;j<8;j++) S += ss[j][lane];
        int dg = end - beg; if (dg < 1) dg = 1;
        float v = S / (float)dg;
        v = (v > 0.f) ? v : expm1f(v);
        uout[(size_t)d0*32 + lane] = v;
        float ww = d_wv[d0];
        int cp = blockIdx.x & (NCPY-1);
        atomicAdd(&d_bnaccM[layer][cp][lane],    ww*v);
        atomicAdd(&d_bnaccM[layer][cp][64+lane], ww*v*v);
    }
}

// ---------------- BN stats: sum copies, produce (a, b') ----------------
__global__ void k_bnstats(const float* __restrict__ g, const float* __restrict__ b,
                          int layer, int cout, float denom, int useTw){
    __shared__ float part[2][128];
    __shared__ float tot[128];
    int t = threadIdx.x;        // 256
    int idx = t & 127, grp = t >> 7;
    float S = 0.f;
    for (int k = grp; k < NCPY; k += 2) S += d_bnaccM[layer][k][idx];
    part[grp][idx] = S;
    __syncthreads();
    if (t < 128) tot[t] = part[0][t] + part[1][t];
    __syncthreads();
    if (t < cout){
        float dn = useTw ? d_twD[0] : denom;
        float m = tot[t]/dn;
        float v = tot[64+t]/dn - m*m;
        float a = g[t]*rsqrtf(v + EPSn);
        d_ssbL[layer][t]    = a;
        d_ssbL[layer][32+t] = b[t] - m*a;
    }
}

// ---------------- pooling ----------------
__global__ void k_poolmax(const float* __restrict__ u){
    int idx = blockIdx.x*blockDim.x + threadIdx.x;
    if (idx >= Nn*32) return;
    int n = idx >> 5, c = idx & 31;
    float v = u[idx]*d_ssbL[5][c] + d_ssbL[5][32+c];
    atomicMax(&d_xpe[d_cid[n]*32 + c], encf(v));
}

__global__ void k_cellfin(){
    int idx = blockIdx.x*blockDim.x + threadIdx.x;
    if (idx >= Sn*32) return;
    int s = idx >> 5, c = idx & 31;
    int cnt = d_ccnt[s];
    if (c == 0){
        float inv = 1.f / (float)(cnt > 1 ? cnt : 1);
        d_pp[2*s]   *= inv;
        d_pp[2*s+1] *= inv;
        float w = (cnt > 0) ? 1.f : 0.f;
        d_wv[s] = w;
        if (cnt > 0) atomicAdd(&d_twD[0], 1.f);
    }
    d_xp[idx] = (cnt > 0) ? decf(d_xpe[idx]) : 0.f;
}

__global__ void k_cedges(const int* __restrict__ src, const int* __restrict__ dst){
    int e = blockIdx.x*blockDim.x + threadIdx.x;
    if (e >= Ee) return;
    int cs = d_cid[src[e]], cd = d_cid[dst[e]];
    if (cs == cd) return;
    int b = cs / Gn;
    int ld = cd - b*Gn;
    if ((unsigned)ld >= (unsigned)Gn) return;
    int key = b*Gn*Gn + (cs - b*Gn)*Gn + ld;
    if (atomicExch(&d_mark[key], 1) == 0){
        int i = atomicAdd(&d_EcD[0], 1);
        d_csrc[i] = cs; d_cdst[i] = cd;
        atomicAdd(&d_degc[cd], 1);
        float cx = d_pp[2*cs]   - d_pp[2*cd];
        float cy = d_pp[2*cs+1] - d_pp[2*cd+1];
        float m = fmaxf(fabsf(cx), fabsf(cy));
        atomicMax(&d_mxD[0], __float_as_uint(m));
    }
}

__global__ void k_scatterC(){
    int i = blockIdx.x*blockDim.x + threadIdx.x;
    if (i >= d_EcD[0]) return;
    int cs = d_csrc[i], cd = d_cdst[i];
    int p = atomicAdd(&d_curc[cd], 1);
    d_csrcP[p] = cs;
    float mx = __uint_as_float(d_mxD[0]);
    float den = 2.f*mx + 1e-12f;
    float f0 = (d_pp[2*cs]   - d_pp[2*cd])   / den + 0.5f;
    float f1 = (d_pp[2*cs+1] - d_pp[2*cd+1]) / den + 0.5f;
    f0 = fminf(fmaxf(f0, 0.f), 1.f);
    f1 = fminf(fmaxf(f1, 0.f), 1.f);
    d_bas2P[p] = make_float4((1.f-f0)*(1.f-f1), f0*(1.f-f1), (1.f-f0)*f1, f0*f1);
}

// ---------------- final: per-batch weighted mean (with BN fold) + FC ----------------
__global__ void k_final(const float* __restrict__ h, const float* __restrict__ fcW,
                        float* __restrict__ out){
    __shared__ float ss[8][33];
    __shared__ float sw8[8];
    __shared__ float gm[32];
    __shared__ float swv;
    int b = blockIdx.x;
    int lane = threadIdx.x & 31, w = threadIdx.x >> 5;
    float a7 = d_ssbL[7][lane], b7 = d_ssbL[7][32+lane];
    float acc = 0.f, accw = 0.f;
    for (int s = b*Gn + w; s < (b+1)*Gn; s += 8){
        float ww = d_wv[s];
        acc  += ww * (a7*h[(size_t)s*32 + lane] + b7);
        accw += ww;
    }
    ss[w][lane] = acc;
    if (lane == 0) sw8[w] = accw;
    __syncthreads();
    if (threadIdx.x < 32){
        float S = 0.f;
        #pragma unroll
        for (int j=0;j<8;j++) S += ss[j][threadIdx.x];
        gm[threadIdx.x] = S;
    }
    if (threadIdx.x == 0){
        float W = 0.f;
        #pragma unroll
        for (int j=0;j<8;j++) W += sw8[j];
        swv = W;
    }
    __syncthreads();
    if (threadIdx.x < 10){
        float o = 0.f;
        #pragma unroll
        for (int c=0;c<32;c++) o += (gm[c]/swv) * fcW[c*10 + threadIdx.x];
        out[b*10 + threadIdx.x] = o;
    }
}

// ---------------- host ----------------
template <typename T>
static T* devptr(const void* sym){
    void* p = nullptr;
    cudaGetSymbolAddress(&p, sym);
    return (T*)p;
}

extern "C" void kernel_launch(void* const* d_in, const int* in_sizes, int n_in,
                              void* d_out, int out_size){
    const float* x     = (const float*)d_in[0];
    const float* pos   = (const float*)d_in[1];
    const int*   batch = (const int*)  d_in[2];
    const int*   ei    = (const int*)  d_in[3];
    const int*   src   = ei;
    const int*   dst   = ei + Ee;
    const float* ea    = (const float*)d_in[4];
    const float* fcW   = (const float*)d_in[29];
    float* out = (float*)d_out;

    float*  pT     = devptr<float>(d_T);
    float*  pU0    = devptr<float>(d_U0);
    float*  pU1    = devptr<float>(d_U1);
    float*  pU2    = devptr<float>(d_U2);
    int*    pdeg   = devptr<int>(d_deg);
    int*    prs    = devptr<int>(d_rs);
    int*    pcur   = devptr<int>(d_cur);
    int*    pesrcP = devptr<int>(d_esrcP);
    float4* pbasP  = devptr<float4>(d_basP);
    int*    pdegc  = devptr<int>(d_degc);
    int*    prsc   = devptr<int>(d_rsc);
    int*    pcurc  = devptr<int>(d_curc);
    int*    pcsrcP = devptr<int>(d_csrcP);
    float4* pbas2P = devptr<float4>(d_bas2P);
    float*  pxp    = devptr<float>(d_xp);
    float*  pC0    = devptr<float>(d_C0);
    float*  pC1    = devptr<float>(d_C1);
    float*  pTc    = devptr<float>(d_Tc);

    // prolog: zero scratch, histogram, CSR build with fused basis scatter
    k_zeros<<<2048,256>>>();
    k_hist<<<Ee/256,256>>>(dst);
    k_prep_nodes<<<Nn/256,256>>>(pos, batch);
    k_scan1<<<256,1024>>>(pdeg, prs, Nn);
    k_scan2<<<1,256>>>(256);
    k_scan3<<<Nn/256,256>>>(pdeg, prs, pcur, Nn);
    k_scatter<<<Ee/256,256>>>(src, dst, ea);

    // fine layers; stats of layer l stored in ssbL[l]
    // l0: W1 (10->8)  in: x raw            -> U0
    k_xform<1><<<Nn/8,256>>>(x, nullptr, (const float*)d_in[5], pT, Nn, 10, 8, -1, -1);
    k_convF<8><<<Nn/32,256>>>(pT, prs, pesrcP, pbasP, pU0, 0, Nn);
    k_bnstats<<<1,256>>>((const float*)d_in[6], (const float*)d_in[7], 0, 8, (float)Nn, 0);
    // l1: W2 (8->16)  in: U0 (slot0)       -> U1
    k_xform<2><<<Nn/8,256>>>(pU0, nullptr, (const float*)d_in[8], pT, Nn, 8, 16, 0, -1);
    k_convF<16><<<Nn/16,256>>>(pT, prs, pesrcP, pbasP, pU1, 1, Nn);
    k_bnstats<<<1,256>>>((const float*)d_in[9], (const float*)d_in[10], 1, 16, (float)Nn, 0);
    // l2: W21 (16->16) in: U1 (slot1)      -> U2 (kept as residual source)
    k_xform<2><<<Nn/8,256>>>(pU1, nullptr, (const float*)d_in[11], pT, Nn, 16, 16, 1, -1);
    k_convF<16><<<Nn/16,256>>>(pT, prs, pesrcP, pbasP, pU2, 2, Nn);
    k_bnstats<<<1,256>>>((const float*)d_in[12], (const float*)d_in[13], 2, 16, (float)Nn, 0);
    // l3: W3 (16->16) in: U2 (slot2)       -> U0
    k_xform<2><<<Nn/8,256>>>(pU2, nullptr, (const float*)d_in[14], pT, Nn, 16, 16, 2, -1);
    k_convF<16><<<Nn/16,256>>>(pT, prs, pesrcP, pbasP, pU0, 3, Nn);
    k_bnstats<<<1,256>>>((const float*)d_in[15], (const float*)d_in[16], 3, 16, (float)Nn, 0);
    // l4: W4 (16->16) in: U0 (slot3)       -> U1
    k_xform<2><<<Nn/8,256>>>(pU0, nullptr, (const float*)d_in[17], pT, Nn, 16, 16, 3, -1);
    k_convF<16><<<Nn/16,256>>>(pT, prs, pesrcP, pbasP, pU1, 4, Nn);
    k_bnstats<<<1,256>>>((const float*)d_in[18], (const float*)d_in[19], 4, 16, (float)Nn, 0);
    // l5: W5 (16->32) in: U1 (slot4) + residual U2 (slot2) -> U0
    k_xform<4><<<Nn/8,256>>>(pU1, pU2, (const float*)d_in[20], pT, Nn, 16, 32, 4, 2);
    k_convF<32><<<Nn/8,256>>>(pT, prs, pesrcP, pbasP, pU0, 5, Nn);
    k_bnstats<<<1,256>>>((const float*)d_in[21], (const float*)d_in[22], 5, 32, (float)Nn, 0);

    // pooling + coarse graph build (BN of layer5 applied inline in poolmax)
    k_poolmax<<<(Nn*32)/256,256>>>(pU0);
    k_cellfin<<<(Sn*32+255)/256,256>>>();
    k_cedges<<<Ee/256,256>>>(src, dst);
    k_scan1<<<(Sn+1023)/1024,1024>>>(pdegc, prsc, Sn);
    k_scan2<<<1,256>>>((Sn+1023)/1024);
    k_scan3<<<(Sn+255)/256,256>>>(pdegc, prsc, pcurc, Sn);
    k_scatterC<<<Ee/256,256>>>();

    // coarse layers (weighted BN): c0 = W6, c1 = W7
    k_xform<4><<<(Sn+7)/8,256>>>(pxp, nullptr, (const float*)d_in[23], pTc, Sn, 32, 32, -1, -1);
    k_convC<<<Sn,256>>>(pTc, prsc, pcsrcP, pbas2P, pC0, 6);
    k_bnstats<<<1,256>>>((const float*)d_in[24], (const float*)d_in[25], 6, 32, 0.f, 1);

    k_xform<4><<<(Sn+7)/8,256>>>(pC0, nullptr, (const float*)d_in[26], pTc, Sn, 32, 32, 6, -1);
    k_convC<<<Sn,256>>>(pTc, prsc, pcsrcP, pbas2P, pC1, 7);
    k_bnstats<<<1,256>>>((const float*)d_in[27], (const float*)d_in[28], 7, 32, 0.f, 1);

    // final: weighted mean with BN fold (slot7) + FC
    k_final<<<Bn,256>>>(pC1, fcW, out);
    (void)in_sizes; (void)n_in; (void)out_size;
}

// round 4
// speedup vs baseline: 1.9011x; 1.3448x over previous
#include <cuda_runtime.h>
#include <cuda_fp16.h>
#include <math.h>

#define Nn   262144
#define Ee   2097152
#define Bn   16
#define GXn  22
#define Gn   484
#define Sn   7744
#define EPSn 1e-5f
#define SXn  (16.0f/346.0f)
#define SYn  (12.0f/260.0f)
#define NCPY 64
#define MARKW ((Bn*Gn*Gn + 31)/32)

// ---------------- scratch (device globals; no allocations) ----------------
__device__ int      d_deg [Nn];
__device__ int      d_rs  [Nn+1];
__device__ int      d_cur [Nn+1];
__device__ int      d_esrcP[Ee];
__device__ uint2    d_basPh[Ee];
__device__ int      d_bsums[256];
__device__ int      d_cid [Nn];
__device__ int      d_ccnt[Sn];
__device__ float    d_pp  [Sn*2];
__device__ unsigned d_xpe [Sn*32];
__device__ float    d_xp  [Sn*32];
__device__ float    d_wv  [Sn];
__device__ unsigned d_markb[MARKW];
__device__ int      d_EcD [1];
__device__ int      d_csrc[Ee];
__device__ int      d_cdst[Ee];
__device__ int      d_degc[Sn];
__device__ int      d_rsc [Sn+1];
__device__ int      d_curc[Sn+1];
__device__ int      d_csrcP[Ee];
__device__ uint2    d_bas2Ph[Ee];
__device__ unsigned d_mxD [1];
__device__ float    d_twD [1];
__device__ uint2    d_Th [(size_t)Nn*32];   // packed half2x2 per channel (max cout=32)
__device__ uint2    d_Tch[(size_t)Sn*32];
__device__ float    d_U0 [(size_t)Nn*32];
__device__ float    d_U1 [(size_t)Nn*32];
__device__ float    d_U2 [(size_t)Nn*32];
__device__ float    d_C0 [Sn*32];
__device__ float    d_C1 [Sn*32];
__device__ float    d_bnaccM[8][NCPY][128];
__device__ float    d_ssbL[8][64];

// ---------------- helpers ----------------
__device__ __forceinline__ unsigned encf(float f){
    unsigned u = __float_as_uint(f);
    return (u & 0x80000000u) ? ~u : (u | 0x80000000u);
}
__device__ __forceinline__ float decf(unsigned u){
    return (u & 0x80000000u) ? __uint_as_float(u & 0x7FFFFFFFu) : __uint_as_float(~u);
}
__device__ __forceinline__ uint2 packb(float b0, float b1, float b2, float b3){
    __half2 h01 = __floats2half2_rn(b0, b1);
    __half2 h23 = __floats2half2_rn(b2, b3);
    uint2 r;
    r.x = *reinterpret_cast<unsigned*>(&h01);
    r.y = *reinterpret_cast<unsigned*>(&h23);
    return r;
}
__device__ __forceinline__ float dot4h(uint2 b, uint2 t){
    float2 bf01 = __half22float2(*reinterpret_cast<__half2*>(&b.x));
    float2 bf23 = __half22float2(*reinterpret_cast<__half2*>(&b.y));
    float2 tf01 = __half22float2(*reinterpret_cast<__half2*>(&t.x));
    float2 tf23 = __half22float2(*reinterpret_cast<__half2*>(&t.y));
    return bf01.x*tf01.x + bf01.y*tf01.y + bf23.x*tf23.x + bf23.y*tf23.y;
}

// ---------------- prolog ----------------
__global__ void k_zeros(){
    int i = blockIdx.x*blockDim.x + threadIdx.x;
    int st = gridDim.x*blockDim.x;
    for (int j=i; j<MARKW;    j+=st) d_markb[j]=0u;
    for (int j=i; j<Nn;       j+=st) d_deg[j]=0;
    for (int j=i; j<Sn;       j+=st){ d_ccnt[j]=0; d_degc[j]=0; }
    for (int j=i; j<Sn*2;     j+=st) d_pp[j]=0.f;
    for (int j=i; j<Sn*32;    j+=st) d_xpe[j]=0u;
    float* bm = &d_bnaccM[0][0][0];
    for (int j=i; j<8*NCPY*128; j+=st) bm[j]=0.f;
    if (i==0){ d_EcD[0]=0; d_mxD[0]=0u; d_twD[0]=0.f; }
}

__global__ void k_hist(const int* __restrict__ dst){
    int e = blockIdx.x*blockDim.x + threadIdx.x;
    if (e >= Ee) return;
    atomicAdd(&d_deg[dst[e]], 1);
}

__global__ void k_prep_nodes(const float* __restrict__ pos, const int* __restrict__ batch){
    int n = blockIdx.x*blockDim.x + threadIdx.x;
    if (n >= Nn) return;
    float px = pos[2*(size_t)n], py = pos[2*(size_t)n+1];
    int cx = min(max((int)floorf(px / SXn), 0), GXn-1);
    int cy = min(max((int)floorf(py / SYn), 0), GXn-1);
    int cid = batch[n]*Gn + cy*GXn + cx;
    d_cid[n] = cid;
    atomicAdd(&d_ccnt[cid], 1);
    atomicAdd(&d_pp[2*cid],   px);
    atomicAdd(&d_pp[2*cid+1], py);
}

// ---------------- exclusive scan (3 kernels) ----------------
__global__ void k_scan1(const int* __restrict__ in, int* __restrict__ out, int n){
    __shared__ int sh[1024];
    int t = threadIdx.x;
    int base = blockIdx.x*1024;
    int v = (base+t < n) ? in[base+t] : 0;
    sh[t] = v; __syncthreads();
    for (int off=1; off<1024; off<<=1){
        int a = (t>=off) ? sh[t-off] : 0;
        __syncthreads();
        sh[t] += a;
        __syncthreads();
    }
    if (base+t < n) out[base+t] = sh[t]-v;
    if (t==1023) d_bsums[blockIdx.x] = sh[1023];
}
__global__ void k_scan2(int nb){
    __shared__ int sh[256];
    int t = threadIdx.x;
    int v = (t<nb) ? d_bsums[t] : 0;
    sh[t] = v; __syncthreads();
    for (int off=1; off<256; off<<=1){
        int a = (t>=off) ? sh[t-off] : 0;
        __syncthreads();
        sh[t] += a;
        __syncthreads();
    }
    if (t<nb) d_bsums[t] = sh[t]-v;
}
__global__ void k_scan3(const int* __restrict__ in, int* __restrict__ out, int* __restrict__ cur, int n){
    int i = blockIdx.x*blockDim.x + threadIdx.x;
    if (i >= n) return;
    int v = out[i] + d_bsums[i>>10];
    out[i] = v; cur[i] = v;
    if (i == n-1){ int tot = v + in[i]; out[n]=tot; cur[n]=tot; }
}

// scatter edges into CSR order, storing src + packed half basis weights
__global__ void k_scatter(const int* __restrict__ src, const int* __restrict__ dst,
                          const float* __restrict__ ea){
    int e = blockIdx.x*blockDim.x + threadIdx.x;
    if (e >= Ee) return;
    float f0 = fminf(fmaxf(ea[2*(size_t)e  ], 0.f), 1.f);
    float f1 = fminf(fmaxf(ea[2*(size_t)e+1], 0.f), 1.f);
    int p = atomicAdd(&d_cur[dst[e]], 1);
    d_esrcP[p] = src[e];
    d_basPh[p] = packb((1.f-f0)*(1.f-f1), f0*(1.f-f1), (1.f-f0)*f1, f0*f1);
}

// ---------------- node transform with BN fold, packed half2 output ----------------
// Th[n][c] = uint2{ half2(t0,t1), half2(t2,t3) } where tk = sum_i in_i * W[k,i,c]
// with in_i = a1_i*X1[n,i] + a2_i*X2[n,i] + (b1_i+b2_i)
template<int COUT>
__global__ void k_xform(const float* __restrict__ X1, const float* __restrict__ X2,
                        const float* __restrict__ W, uint2* __restrict__ Th,
                        int nrows, int cin, int ab1, int ab2){
    constexpr int K4 = 4*COUT;
    constexpr int LC = 32/COUT;
    __shared__ float Wsh[32*128];
    __shared__ float A1[32], B1[32], A2[32], B2[32];
    __shared__ float CB[128];
    for (int idx = threadIdx.x; idx < cin*K4; idx += blockDim.x)
        Wsh[idx] = W[idx];           // W laid out [k][i][c] == [k*cin+i][c]; reindex below
    __syncthreads();
    // note: W global layout is (4, cin, cout): element (k,i,c) at ((k*cin+i)*COUT + c).
    // Wsh mirrors that exactly (contiguous copy), so index Wsh[(k*cin+i)*COUT + c].
    if (threadIdx.x < 32){
        int i = threadIdx.x;
        A1[i] = (ab1 >= 0) ? d_ssbL[ab1][i]    : 1.f;
        B1[i] = (ab1 >= 0) ? d_ssbL[ab1][32+i] : 0.f;
        A2[i] = (ab2 >= 0) ? d_ssbL[ab2][i]    : 0.f;
        B2[i] = (ab2 >= 0) ? d_ssbL[ab2][32+i] : 0.f;
    }
    __syncthreads();
    for (int o = threadIdx.x; o < K4; o += blockDim.x){
        int k = o / COUT, c = o - k*COUT;
        float s = 0.f;
        for (int i = 0; i < cin; i++) s += (B1[i]+B2[i])*Wsh[(k*cin+i)*COUT + c];
        CB[o] = s;
    }
    __syncthreads();
    int w = threadIdx.x >> 5, lane = threadIdx.x & 31;
    int c   = lane & (COUT-1);
    int sub = lane >> (COUT==32 ? 5 : (COUT==16 ? 4 : 3));
    int n = (blockIdx.x*8 + w)*LC + sub;
    if (n >= nrows) return;
    const float* x1 = X1 + (size_t)n*cin;
    const float* x2 = X2 ? (X2 + (size_t)n*cin) : nullptr;
    float a0 = CB[c], a1 = CB[COUT+c], a2 = CB[2*COUT+c], a3 = CB[3*COUT+c];
    for (int i = 0; i < cin; i++){
        float xi = A1[i]*x1[i];
        if (x2) xi += A2[i]*x2[i];
        a0 += xi*Wsh[(0*cin+i)*COUT + c];
        a1 += xi*Wsh[(1*cin+i)*COUT + c];
        a2 += xi*Wsh[(2*cin+i)*COUT + c];
        a3 += xi*Wsh[(3*cin+i)*COUT + c];
    }
    Th[(size_t)n*COUT + c] = packb(a0, a1, a2, a3);
}

// ---------------- fine conv: 32/COUT dst per warp, fused BN reduce ----------------
template<int COUT>
__global__ void k_convF(const uint2* __restrict__ Th, const int* __restrict__ rs,
                        const int* __restrict__ esrcP, const uint2* __restrict__ basPh,
                        float* __restrict__ uout, int layer, int ndst){
    constexpr int LC = 32/COUT;
    int lane = threadIdx.x & 31, w = threadIdx.x >> 5;
    int c = lane & (COUT-1);
    int sub = lane / COUT;
    int gw = blockIdx.x*8 + w;
    int d0 = gw*LC + sub;
    float acc = 0.f, acc2 = 0.f; int beg = 0, end = 0;
    if (d0 < ndst){ beg = rs[d0]; end = rs[d0+1]; }
    int p = beg;
    for (; p + 1 < end; p += 2){
        int s0 = esrcP[p], s1 = esrcP[p+1];
        uint2 b0 = basPh[p], b1 = basPh[p+1];
        uint2 t0 = Th[(size_t)s0*COUT + c];
        uint2 t1 = Th[(size_t)s1*COUT + c];
        acc  += dot4h(b0, t0);
        acc2 += dot4h(b1, t1);
    }
    if (p < end){
        int s0 = esrcP[p];
        uint2 b0 = basPh[p];
        uint2 t0 = Th[(size_t)s0*COUT + c];
        acc += dot4h(b0, t0);
    }
    acc += acc2;
    float v = 0.f;
    if (d0 < ndst){
        int dg = end - beg; if (dg < 1) dg = 1;
        v = acc / (float)dg;
        v = (v > 0.f) ? v : expm1f(v);
        uout[(size_t)d0*COUT + c] = v;
    }
    __shared__ float ss[8][33], sq[8][33];
    ss[w][lane] = v; sq[w][lane] = v*v;
    __syncthreads();
    if (w == 0 && lane < COUT){
        float S = 0.f, Q = 0.f;
        #pragma unroll
        for (int j=0;j<8;j++){
            #pragma unroll
            for (int t=0;t<LC;t++){ S += ss[j][lane + t*COUT]; Q += sq[j][lane + t*COUT]; }
        }
        int cp = blockIdx.x & (NCPY-1);
        atomicAdd(&d_bnaccM[layer][cp][lane],    S);
        atomicAdd(&d_bnaccM[layer][cp][64+lane], Q);
    }
}

// ---------------- coarse conv: block per dst (high degree), weighted BN reduce --------
__global__ void k_convC(const uint2* __restrict__ Th, const int* __restrict__ rs,
                        const int* __restrict__ esrcP, const uint2* __restrict__ basPh,
                        float* __restrict__ uout, int layer){
    int d0 = blockIdx.x;
    int lane = threadIdx.x & 31, w = threadIdx.x >> 5;
    int beg = rs[d0], end = rs[d0+1];
    float acc = 0.f, acc2 = 0.f;
    int p = beg + w*2;
    for (; p + 1 < end; p += 16){
        int s0 = esrcP[p], s1 = esrcP[p+1];
        uint2 b0 = basPh[p], b1 = basPh[p+1];
        uint2 t0 = Th[(size_t)s0*32 + lane];
        uint2 t1 = Th[(size_t)s1*32 + lane];
        acc  += dot4h(b0, t0);
        acc2 += dot4h(b1, t1);
    }
    if (p < end){
        int s0 = esrcP[p];
        uint2 b0 = basPh[p];
        uint2 t0 = Th[(size_t)s0*32 + lane];
        acc += dot4h(b0, t0);
    }
    acc += acc2;
    __shared__ float ss[8][33];
    ss[w][lane] = acc; __syncthreads();
    if (w == 0){
        float S = 0.f;
        #pragma unroll
        for (int j=0;j<8;j++) S += ss[j][lane];
        int dg = end - beg; if (dg < 1) dg = 1;
        float v = S / (float)dg;
        v = (v > 0.f) ? v : expm1f(v);
        uout[(size_t)d0*32 + lane] = v;
        float ww = d_wv[d0];
        int cp = blockIdx.x & (NCPY-1);
        atomicAdd(&d_bnaccM[layer][cp][lane],    ww*v);
        atomicAdd(&d_bnaccM[layer][cp][64+lane], ww*v*v);
    }
}

// ---------------- BN stats: sum copies, produce (a, b') ----------------
__global__ void k_bnstats(const float* __restrict__ g, const float* __restrict__ b,
                          int layer, int cout, float denom, int useTw){
    __shared__ float part[2][128];
    __shared__ float tot[128];
    int t = threadIdx.x;        // 256
    int idx = t & 127, grp = t >> 7;
    float S = 0.f;
    for (int k = grp; k < NCPY; k += 2) S += d_bnaccM[layer][k][idx];
    part[grp][idx] = S;
    __syncthreads();
    if (t < 128) tot[t] = part[0][t] + part[1][t];
    __syncthreads();
    if (t < cout){
        float dn = useTw ? d_twD[0] : denom;
        float m = tot[t]/dn;
        float v = tot[64+t]/dn - m*m;
        float a = g[t]*rsqrtf(v + EPSn);
        d_ssbL[layer][t]    = a;
        d_ssbL[layer][32+t] = b[t] - m*a;
    }
}

// ---------------- pooling ----------------
__global__ void k_poolmax(const float* __restrict__ u){
    int idx = blockIdx.x*blockDim.x + threadIdx.x;
    if (idx >= Nn*32) return;
    int n = idx >> 5, c = idx & 31;
    float v = u[idx]*d_ssbL[5][c] + d_ssbL[5][32+c];
    atomicMax(&d_xpe[d_cid[n]*32 + c], encf(v));
}

__global__ void k_cellfin(){
    int idx = blockIdx.x*blockDim.x + threadIdx.x;
    if (idx >= Sn*32) return;
    int s = idx >> 5, c = idx & 31;
    int cnt = d_ccnt[s];
    if (c == 0){
        float inv = 1.f / (float)(cnt > 1 ? cnt : 1);
        d_pp[2*s]   *= inv;
        d_pp[2*s+1] *= inv;
        float w = (cnt > 0) ? 1.f : 0.f;
        d_wv[s] = w;
        if (cnt > 0) atomicAdd(&d_twD[0], 1.f);
    }
    d_xp[idx] = (cnt > 0) ? decf(d_xpe[idx]) : 0.f;
}

__global__ void k_cedges(const int* __restrict__ src, const int* __restrict__ dst){
    int e = blockIdx.x*blockDim.x + threadIdx.x;
    if (e >= Ee) return;
    int cs = d_cid[src[e]], cd = d_cid[dst[e]];
    if (cs == cd) return;
    int b = cs / Gn;
    int ld = cd - b*Gn;
    if ((unsigned)ld >= (unsigned)Gn) return;
    int key = b*Gn*Gn + (cs - b*Gn)*Gn + ld;
    unsigned bit = 1u << (key & 31);
    unsigned old = atomicOr(&d_markb[key >> 5], bit);
    if (!(old & bit)){
        int i = atomicAdd(&d_EcD[0], 1);
        d_csrc[i] = cs; d_cdst[i] = cd;
        atomicAdd(&d_degc[cd], 1);
        float cx = d_pp[2*cs]   - d_pp[2*cd];
        float cy = d_pp[2*cs+1] - d_pp[2*cd+1];
        float m = fmaxf(fabsf(cx), fabsf(cy));
        atomicMax(&d_mxD[0], __float_as_uint(m));
    }
}

__global__ void k_scatterC(){
    int i = blockIdx.x*blockDim.x + threadIdx.x;
    if (i >= d_EcD[0]) return;
    int cs = d_csrc[i], cd = d_cdst[i];
    int p = atomicAdd(&d_curc[cd], 1);
    d_csrcP[p] = cs;
    float mx = __uint_as_float(d_mxD[0]);
    float den = 2.f*mx + 1e-12f;
    float f0 = (d_pp[2*cs]   - d_pp[2*cd])   / den + 0.5f;
    float f1 = (d_pp[2*cs+1] - d_pp[2*cd+1]) / den + 0.5f;
    f0 = fminf(fmaxf(f0, 0.f), 1.f);
    f1 = fminf(fmaxf(f1, 0.f), 1.f);
    d_bas2Ph[p] = packb((1.f-f0)*(1.f-f1), f0*(1.f-f1), (1.f-f0)*f1, f0*f1);
}

// ---------------- final: per-batch weighted mean (with BN fold) + FC ----------------
__global__ void k_final(const float* __restrict__ h, const float* __restrict__ fcW,
                        float* __restrict__ out){
    __shared__ float ss[8][33];
    __shared__ float sw8[8];
    __shared__ float gm[32];
    __shared__ float swv;
    int b = blockIdx.x;
    int lane = threadIdx.x & 31, w = threadIdx.x >> 5;
    float a7 = d_ssbL[7][lane], b7 = d_ssbL[7][32+lane];
    float acc = 0.f, accw = 0.f;
    for (int s = b*Gn + w; s < (b+1)*Gn; s += 8){
        float ww = d_wv[s];
        acc  += ww * (a7*h[(size_t)s*32 + lane] + b7);
        accw += ww;
    }
    ss[w][lane] = acc;
    if (lane == 0) sw8[w] = accw;
    __syncthreads();
    if (threadIdx.x < 32){
        float S = 0.f;
        #pragma unroll
        for (int j=0;j<8;j++) S += ss[j][threadIdx.x];
        gm[threadIdx.x] = S;
    }
    if (threadIdx.x == 0){
        float W = 0.f;
        #pragma unroll
        for (int j=0;j<8;j++) W += sw8[j];
        swv = W;
    }
    __syncthreads();
    if (threadIdx.x < 10){
        float o = 0.f;
        #pragma unroll
        for (int c=0;c<32;c++) o += (gm[c]/swv) * fcW[c*10 + threadIdx.x];
        out[b*10 + threadIdx.x] = o;
    }
}

// ---------------- host ----------------
template <typename T>
static T* devptr(const void* sym){
    void* p = nullptr;
    cudaGetSymbolAddress(&p, sym);
    return (T*)p;
}

extern "C" void kernel_launch(void* const* d_in, const int* in_sizes, int n_in,
                              void* d_out, int out_size){
    const float* x     = (const float*)d_in[0];
    const float* pos   = (const float*)d_in[1];
    const int*   batch = (const int*)  d_in[2];
    const int*   ei    = (const int*)  d_in[3];
    const int*   src   = ei;
    const int*   dst   = ei + Ee;
    const float* ea    = (const float*)d_in[4];
    const float* fcW   = (const float*)d_in[29];
    float* out = (float*)d_out;

    uint2*  pTh    = devptr<uint2>(d_Th);
    uint2*  pTch   = devptr<uint2>(d_Tch);
    float*  pU0    = devptr<float>(d_U0);
    float*  pU1    = devptr<float>(d_U1);
    float*  pU2    = devptr<float>(d_U2);
    int*    pdeg   = devptr<int>(d_deg);
    int*    prs    = devptr<int>(d_rs);
    int*    pcur   = devptr<int>(d_cur);
    int*    pesrcP = devptr<int>(d_esrcP);
    uint2*  pbasPh = devptr<uint2>(d_basPh);
    int*    pdegc  = devptr<int>(d_degc);
    int*    prsc   = devptr<int>(d_rsc);
    int*    pcurc  = devptr<int>(d_curc);
    int*    pcsrcP = devptr<int>(d_csrcP);
    uint2*  pbas2Ph= devptr<uint2>(d_bas2Ph);
    float*  pxp    = devptr<float>(d_xp);
    float*  pC0    = devptr<float>(d_C0);
    float*  pC1    = devptr<float>(d_C1);

    // prolog: zero scratch, histogram, CSR build with fused basis scatter
    k_zeros<<<2048,256>>>();
    k_hist<<<Ee/256,256>>>(dst);
    k_prep_nodes<<<Nn/256,256>>>(pos, batch);
    k_scan1<<<256,1024>>>(pdeg, prs, Nn);
    k_scan2<<<1,256>>>(256);
    k_scan3<<<Nn/256,256>>>(pdeg, prs, pcur, Nn);
    k_scatter<<<Ee/256,256>>>(src, dst, ea);

    // fine layers; stats of layer l stored in ssbL[l]
    // l0: W1 (10->8)  in: x raw            -> U0
    k_xform<8><<<Nn/32,256>>>(x, nullptr, (const float*)d_in[5], pTh, Nn, 10, -1, -1);
    k_convF<8><<<Nn/32,256>>>(pTh, prs, pesrcP, pbasPh, pU0, 0, Nn);
    k_bnstats<<<1,256>>>((const float*)d_in[6], (const float*)d_in[7], 0, 8, (float)Nn, 0);
    // l1: W2 (8->16)  in: U0 (slot0)       -> U1
    k_xform<16><<<Nn/16,256>>>(pU0, nullptr, (const float*)d_in[8], pTh, Nn, 8, 0, -1);
    k_convF<16><<<Nn/16,256>>>(pTh, prs, pesrcP, pbasPh, pU1, 1, Nn);
    k_bnstats<<<1,256>>>((const float*)d_in[9], (const float*)d_in[10], 1, 16, (float)Nn, 0);
    // l2: W21 (16->16) in: U1 (slot1)      -> U2 (kept as residual source)
    k_xform<16><<<Nn/16,256>>>(pU1, nullptr, (const float*)d_in[11], pTh, Nn, 16, 1, -1);
    k_convF<16><<<Nn/16,256>>>(pTh, prs, pesrcP, pbasPh, pU2, 2, Nn);
    k_bnstats<<<1,256>>>((const float*)d_in[12], (const float*)d_in[13], 2, 16, (float)Nn, 0);
    // l3: W3 (16->16) in: U2 (slot2)       -> U0
    k_xform<16><<<Nn/16,256>>>(pU2, nullptr, (const float*)d_in[14], pTh, Nn, 16, 2, -1);
    k_convF<16><<<Nn/16,256>>>(pTh, prs, pesrcP, pbasPh, pU0, 3, Nn);
    k_bnstats<<<1,256>>>((const float*)d_in[15], (const float*)d_in[16], 3, 16, (float)Nn, 0);
    // l4: W4 (16->16) in: U0 (slot3)       -> U1
    k_xform<16><<<Nn/16,256>>>(pU0, nullptr, (const float*)d_in[17], pTh, Nn, 16, 3, -1);
    k_convF<16><<<Nn/16,256>>>(pTh, prs, pesrcP, pbasPh, pU1, 4, Nn);
    k_bnstats<<<1,256>>>((const float*)d_in[18], (const float*)d_in[19], 4, 16, (float)Nn, 0);
    // l5: W5 (16->32) in: U1 (slot4) + residual U2 (slot2) -> U0
    k_xform<32><<<Nn/8,256>>>(pU1, pU2, (const float*)d_in[20], pTh, Nn, 16, 4, 2);
    k_convF<32><<<Nn/8,256>>>(pTh, prs, pesrcP, pbasPh, pU0, 5, Nn);
    k_bnstats<<<1,256>>>((const float*)d_in[21], (const float*)d_in[22], 5, 32, (float)Nn, 0);

    // pooling + coarse graph build (BN of layer5 applied inline in poolmax)
    k_poolmax<<<(Nn*32)/256,256>>>(pU0);
    k_cellfin<<<(Sn*32+255)/256,256>>>();
    k_cedges<<<Ee/256,256>>>(src, dst);
    k_scan1<<<(Sn+1023)/1024,1024>>>(pdegc, prsc, Sn);
    k_scan2<<<1,256>>>((Sn+1023)/1024);
    k_scan3<<<(Sn+255)/256,256>>>(pdegc, prsc, pcurc, Sn);
    k_scatterC<<<Ee/256,256>>>();

    // coarse layers (weighted BN): c0 = W6, c1 = W7
    k_xform<32><<<(Sn+7)/8,256>>>(pxp, nullptr, (const float*)d_in[23], pTch, Sn, 32, -1, -1);
    k_convC<<<Sn,256>>>(pTch, prsc, pcsrcP, pbas2Ph, pC0, 6);
    k_bnstats<<<1,256>>>((const float*)d_in[24], (const float*)d_in[25], 6, 32, 0.f, 1);

    k_xform<32><<<(Sn+7)/8,256>>>(pC0, nullptr, (const float*)d_in[26], pTch, Sn, 32, 6, -1);
    k_convC<<<Sn,256>>>(pTch, prsc, pcsrcP, pbas2Ph, pC1, 7);
    k_bnstats<<<1,256>>>((const float*)d_in[27], (const float*)d_in[28], 7, 32, 0.f, 1);

    // final: weighted mean with BN fold (slot7) + FC
    k_final<<<Bn,256>>>(pC1, fcW, out);
    (void)in_sizes; (void)n_in; (void)out_size;
}

// round 5
// speedup vs baseline: 2.0980x; 1.1036x over previous
#include <cuda_runtime.h>
#include <cuda_fp16.h>
#include <math.h>

#define Nn   262144
#define Ee   2097152
#define Bn   16
#define GXn  22
#define Gn   484
#define Sn   7744
#define EPSn 1e-5f
#define SXn  (16.0f/346.0f)
#define SYn  (12.0f/260.0f)
#define NCPY 64
#define MARKW ((Bn*Gn*Gn + 31)/32)

// ---------------- scratch (device globals; no allocations) ----------------
__device__ int      d_deg [Nn];
__device__ int      d_rs  [Nn+1];
__device__ int      d_cur [Nn+1];
__device__ uint2    d_eP  [Ee];      // packed: src(18b)+b2(14b) | b0(16b)+b1(16b)
__device__ int      d_bsums[256];
__device__ int      d_cid [Nn];
__device__ int      d_ccnt[Sn];
__device__ float    d_pp  [Sn*2];
__device__ unsigned d_xpe [Sn*32];
__device__ float    d_xp  [Sn*32];
__device__ float    d_wv  [Sn];
__device__ unsigned d_markb[MARKW];
__device__ int      d_EcD [1];
__device__ int      d_csrc[Ee];
__device__ int      d_cdst[Ee];
__device__ int      d_degc[Sn];
__device__ int      d_rsc [Sn+1];
__device__ int      d_curc[Sn+1];
__device__ uint2    d_ePc [Ee];
__device__ unsigned d_mxD [1];
__device__ float    d_twD [1];
__device__ uint2    d_Th [(size_t)Nn*32];   // packed half2x2 per channel (max cout=32)
__device__ uint2    d_Tch[(size_t)Sn*32];
__device__ float    d_U0 [(size_t)Nn*32];
__device__ float    d_U1 [(size_t)Nn*32];
__device__ float    d_U2 [(size_t)Nn*32];
__device__ float    d_C0 [Sn*32];
__device__ float    d_C1 [Sn*32];
__device__ float    d_bnaccM[8][NCPY][128];
__device__ float    d_ssbL[8][64];

// ---------------- helpers ----------------
__device__ __forceinline__ unsigned encf(float f){
    unsigned u = __float_as_uint(f);
    return (u & 0x80000000u) ? ~u : (u | 0x80000000u);
}
__device__ __forceinline__ float decf(unsigned u){
    return (u & 0x80000000u) ? __uint_as_float(u & 0x7FFFFFFFu) : __uint_as_float(~u);
}
__device__ __forceinline__ uint2 pack_edge(int s, float b0, float b1, float b2){
    unsigned q0 = (unsigned)__float2int_rn(b0*65535.f);
    unsigned q1 = (unsigned)__float2int_rn(b1*65535.f);
    unsigned q2 = (unsigned)__float2int_rn(b2*16383.f);
    uint2 r;
    r.x = ((unsigned)s << 14) | q2;
    r.y = q0 | (q1 << 16);
    return r;
}
__device__ __forceinline__ void unpack_edge(uint2 e, int& s, float& b0, float& b1,
                                            float& b2, float& b3){
    s  = (int)(e.x >> 14);
    b2 = (float)(e.x & 0x3FFFu) * (1.f/16383.f);
    b0 = (float)(e.y & 0xFFFFu) * (1.f/65535.f);
    b1 = (float)(e.y >> 16)     * (1.f/65535.f);
    b3 = 1.f - b0 - b1 - b2;
}
__device__ __forceinline__ float dot4e(uint2 e, uint2 t, int& s){
    float b0,b1,b2,b3;
    unpack_edge(e, s, b0, b1, b2, b3);
    float2 t01 = __half22float2(*reinterpret_cast<__half2*>(&t.x));
    float2 t23 = __half22float2(*reinterpret_cast<__half2*>(&t.y));
    return b0*t01.x + b1*t01.y + b2*t23.x + b3*t23.y;
}
__device__ __forceinline__ uint2 packh(float a0, float a1, float a2, float a3){
    __half2 h01 = __floats2half2_rn(a0, a1);
    __half2 h23 = __floats2half2_rn(a2, a3);
    uint2 r;
    r.x = *reinterpret_cast<unsigned*>(&h01);
    r.y = *reinterpret_cast<unsigned*>(&h23);
    return r;
}

// ---------------- prolog ----------------
__global__ void k_zeros(){
    int i = blockIdx.x*blockDim.x + threadIdx.x;
    int st = gridDim.x*blockDim.x;
    for (int j=i; j<MARKW;    j+=st) d_markb[j]=0u;
    for (int j=i; j<Nn;       j+=st) d_deg[j]=0;
    for (int j=i; j<Sn;       j+=st){ d_ccnt[j]=0; d_degc[j]=0; }
    for (int j=i; j<Sn*2;     j+=st) d_pp[j]=0.f;
    for (int j=i; j<Sn*32;    j+=st) d_xpe[j]=0u;
    float* bm = &d_bnaccM[0][0][0];
    for (int j=i; j<8*NCPY*128; j+=st) bm[j]=0.f;
    if (i==0){ d_EcD[0]=0; d_mxD[0]=0u; d_twD[0]=0.f; }
}

// fused: edge dst histogram + node cell assignment
__global__ void k_prep(const int* __restrict__ dst, const float* __restrict__ pos,
                       const int* __restrict__ batch){
    int e = blockIdx.x*blockDim.x + threadIdx.x;
    if (e < Ee) atomicAdd(&d_deg[dst[e]], 1);
    if (e < Nn){
        float px = pos[2*(size_t)e], py = pos[2*(size_t)e+1];
        int cx = min(max((int)floorf(px / SXn), 0), GXn-1);
        int cy = min(max((int)floorf(py / SYn), 0), GXn-1);
        int cid = batch[e]*Gn + cy*GXn + cx;
        d_cid[e] = cid;
        atomicAdd(&d_ccnt[cid], 1);
        atomicAdd(&d_pp[2*cid],   px);
        atomicAdd(&d_pp[2*cid+1], py);
    }
}

// ---------------- exclusive scan (3 kernels) ----------------
__global__ void k_scan1(const int* __restrict__ in, int* __restrict__ out, int n){
    __shared__ int sh[1024];
    int t = threadIdx.x;
    int base = blockIdx.x*1024;
    int v = (base+t < n) ? in[base+t] : 0;
    sh[t] = v; __syncthreads();
    for (int off=1; off<1024; off<<=1){
        int a = (t>=off) ? sh[t-off] : 0;
        __syncthreads();
        sh[t] += a;
        __syncthreads();
    }
    if (base+t < n) out[base+t] = sh[t]-v;
    if (t==1023) d_bsums[blockIdx.x] = sh[1023];
}
__global__ void k_scan2(int nb){
    __shared__ int sh[256];
    int t = threadIdx.x;
    int v = (t<nb) ? d_bsums[t] : 0;
    sh[t] = v; __syncthreads();
    for (int off=1; off<256; off<<=1){
        int a = (t>=off) ? sh[t-off] : 0;
        __syncthreads();
        sh[t] += a;
        __syncthreads();
    }
    if (t<nb) d_bsums[t] = sh[t]-v;
}
__global__ void k_scan3(const int* __restrict__ in, int* __restrict__ out, int* __restrict__ cur, int n){
    int i = blockIdx.x*blockDim.x + threadIdx.x;
    if (i >= n) return;
    int v = out[i] + d_bsums[i>>10];
    out[i] = v; cur[i] = v;
    if (i == n-1){ int tot = v + in[i]; out[n]=tot; cur[n]=tot; }
}

// scatter edges into CSR order as packed uint2
__global__ void k_scatter(const int* __restrict__ src, const int* __restrict__ dst,
                          const float* __restrict__ ea){
    int e = blockIdx.x*blockDim.x + threadIdx.x;
    if (e >= Ee) return;
    float f0 = fminf(fmaxf(ea[2*(size_t)e  ], 0.f), 1.f);
    float f1 = fminf(fmaxf(ea[2*(size_t)e+1], 0.f), 1.f);
    int p = atomicAdd(&d_cur[dst[e]], 1);
    d_eP[p] = pack_edge(src[e], (1.f-f0)*(1.f-f1), f0*(1.f-f1), (1.f-f0)*f1);
}

// ---------------- node transform with BN fold, packed half2 output ----------------
template<int COUT>
__global__ void k_xform(const float* __restrict__ X1, const float* __restrict__ X2,
                        const float* __restrict__ W, uint2* __restrict__ Th,
                        int nrows, int cin, int ab1, int ab2){
    constexpr int K4 = 4*COUT;
    constexpr int LC = 32/COUT;
    __shared__ float Wsh[32*128];
    __shared__ float A1[32], B1[32], A2[32], B2[32];
    __shared__ float CB[128];
    for (int idx = threadIdx.x; idx < cin*K4; idx += blockDim.x)
        Wsh[idx] = W[idx];
    __syncthreads();
    if (threadIdx.x < 32){
        int i = threadIdx.x;
        A1[i] = (ab1 >= 0) ? d_ssbL[ab1][i]    : 1.f;
        B1[i] = (ab1 >= 0) ? d_ssbL[ab1][32+i] : 0.f;
        A2[i] = (ab2 >= 0) ? d_ssbL[ab2][i]    : 0.f;
        B2[i] = (ab2 >= 0) ? d_ssbL[ab2][32+i] : 0.f;
    }
    __syncthreads();
    for (int o = threadIdx.x; o < K4; o += blockDim.x){
        int k = o / COUT, c = o - k*COUT;
        float s = 0.f;
        for (int i = 0; i < cin; i++) s += (B1[i]+B2[i])*Wsh[(k*cin+i)*COUT + c];
        CB[o] = s;
    }
    __syncthreads();
    int w = threadIdx.x >> 5, lane = threadIdx.x & 31;
    int c   = lane & (COUT-1);
    int sub = lane >> (COUT==32 ? 5 : (COUT==16 ? 4 : 3));
    int n = (blockIdx.x*8 + w)*LC + sub;
    if (n >= nrows) return;
    const float* x1 = X1 + (size_t)n*cin;
    const float* x2 = X2 ? (X2 + (size_t)n*cin) : nullptr;
    float a0 = CB[c], a1 = CB[COUT+c], a2 = CB[2*COUT+c], a3 = CB[3*COUT+c];
    for (int i = 0; i < cin; i++){
        float xi = A1[i]*x1[i];
        if (x2) xi += A2[i]*x2[i];
        a0 += xi*Wsh[(0*cin+i)*COUT + c];
        a1 += xi*Wsh[(1*cin+i)*COUT + c];
        a2 += xi*Wsh[(2*cin+i)*COUT + c];
        a3 += xi*Wsh[(3*cin+i)*COUT + c];
    }
    Th[(size_t)n*COUT + c] = packh(a0, a1, a2, a3);
}

// ---------------- fine conv: 32/COUT dst per warp, fused BN reduce ----------------
template<int COUT>
__global__ void k_convF(const uint2* __restrict__ Th, const int* __restrict__ rs,
                        const uint2* __restrict__ eP,
                        float* __restrict__ uout, int layer, int ndst){
    constexpr int LC = 32/COUT;
    int lane = threadIdx.x & 31, w = threadIdx.x >> 5;
    int c = lane & (COUT-1);
    int sub = lane / COUT;
    int gw = blockIdx.x*8 + w;
    int d0 = gw*LC + sub;
    float acc = 0.f, acc2 = 0.f; int beg = 0, end = 0;
    if (d0 < ndst){ beg = rs[d0]; end = rs[d0+1]; }
    int p = beg;
    for (; p + 1 < end; p += 2){
        uint2 e0 = eP[p], e1 = eP[p+1];
        int s0 = (int)(e0.x >> 14), s1 = (int)(e1.x >> 14);
        uint2 t0 = Th[(size_t)s0*COUT + c];
        uint2 t1 = Th[(size_t)s1*COUT + c];
        int du;
        acc  += dot4e(e0, t0, du);
        acc2 += dot4e(e1, t1, du);
    }
    if (p < end){
        uint2 e0 = eP[p];
        int s0 = (int)(e0.x >> 14);
        uint2 t0 = Th[(size_t)s0*COUT + c];
        int du;
        acc += dot4e(e0, t0, du);
    }
    acc += acc2;
    float v = 0.f;
    if (d0 < ndst){
        int dg = end - beg; if (dg < 1) dg = 1;
        v = acc / (float)dg;
        v = (v > 0.f) ? v : expm1f(v);
        uout[(size_t)d0*COUT + c] = v;
    }
    __shared__ float ss[8][33], sq[8][33];
    ss[w][lane] = v; sq[w][lane] = v*v;
    __syncthreads();
    if (w == 0 && lane < COUT){
        float S = 0.f, Q = 0.f;
        #pragma unroll
        for (int j=0;j<8;j++){
            #pragma unroll
            for (int t=0;t<LC;t++){ S += ss[j][lane + t*COUT]; Q += sq[j][lane + t*COUT]; }
        }
        int cp = blockIdx.x & (NCPY-1);
        atomicAdd(&d_bnaccM[layer][cp][lane],    S);
        atomicAdd(&d_bnaccM[layer][cp][64+lane], Q);
    }
}

// ---------------- coarse conv: block per dst, weighted BN reduce ----------------
__global__ void k_convC(const uint2* __restrict__ Th, const int* __restrict__ rs,
                        const uint2* __restrict__ eP,
                        float* __restrict__ uout, int layer){
    int d0 = blockIdx.x;
    int lane = threadIdx.x & 31, w = threadIdx.x >> 5;
    int beg = rs[d0], end = rs[d0+1];
    float acc = 0.f, acc2 = 0.f;
    int p = beg + w*2;
    for (; p + 1 < end; p += 16){
        uint2 e0 = eP[p], e1 = eP[p+1];
        int s0 = (int)(e0.x >> 14), s1 = (int)(e1.x >> 14);
        uint2 t0 = Th[(size_t)s0*32 + lane];
        uint2 t1 = Th[(size_t)s1*32 + lane];
        int du;
        acc  += dot4e(e0, t0, du);
        acc2 += dot4e(e1, t1, du);
    }
    if (p < end){
        uint2 e0 = eP[p];
        int s0 = (int)(e0.x >> 14);
        uint2 t0 = Th[(size_t)s0*32 + lane];
        int du;
        acc += dot4e(e0, t0, du);
    }
    acc += acc2;
    __shared__ float ss[8][33];
    ss[w][lane] = acc; __syncthreads();
    if (w == 0){
        float S = 0.f;
        #pragma unroll
        for (int j=0;j<8;j++) S += ss[j][lane];
        int dg = end - beg; if (dg < 1) dg = 1;
        float v = S / (float)dg;
        v = (v > 0.f) ? v : expm1f(v);
        uout[(size_t)d0*32 + lane] = v;
        float ww = d_wv[d0];
        int cp = blockIdx.x & (NCPY-1);
        atomicAdd(&d_bnaccM[layer][cp][lane],    ww*v);
        atomicAdd(&d_bnaccM[layer][cp][64+lane], ww*v*v);
    }
}

// ---------------- BN stats ----------------
__global__ void k_bnstats(const float* __restrict__ g, const float* __restrict__ b,
                          int layer, int cout, float denom, int useTw){
    __shared__ float part[2][128];
    __shared__ float tot[128];
    int t = threadIdx.x;        // 256
    int idx = t & 127, grp = t >> 7;
    float S = 0.f;
    for (int k = grp; k < NCPY; k += 2) S += d_bnaccM[layer][k][idx];
    part[grp][idx] = S;
    __syncthreads();
    if (t < 128) tot[t] = part[0][t] + part[1][t];
    __syncthreads();
    if (t < cout){
        float dn = useTw ? d_twD[0] : denom;
        float m = tot[t]/dn;
        float v = tot[64+t]/dn - m*m;
        float a = g[t]*rsqrtf(v + EPSn);
        d_ssbL[layer][t]    = a;
        d_ssbL[layer][32+t] = b[t] - m*a;
    }
}

// ---------------- pooling ----------------
__global__ void k_poolmax(const float* __restrict__ u){
    int idx = blockIdx.x*blockDim.x + threadIdx.x;
    if (idx >= Nn*32) return;
    int n = idx >> 5, c = idx & 31;
    float v = u[idx]*d_ssbL[5][c] + d_ssbL[5][32+c];
    atomicMax(&d_xpe[d_cid[n]*32 + c], encf(v));
}

__global__ void k_cellfin(){
    int idx = blockIdx.x*blockDim.x + threadIdx.x;
    if (idx >= Sn*32) return;
    int s = idx >> 5, c = idx & 31;
    int cnt = d_ccnt[s];
    if (c == 0){
        float inv = 1.f / (float)(cnt > 1 ? cnt : 1);
        d_pp[2*s]   *= inv;
        d_pp[2*s+1] *= inv;
        float w = (cnt > 0) ? 1.f : 0.f;
        d_wv[s] = w;
        if (cnt > 0) atomicAdd(&d_twD[0], 1.f);
    }
    d_xp[idx] = (cnt > 0) ? decf(d_xpe[idx]) : 0.f;
}

// coarse edge dedup with warp-aggregated counter + max (kills single-address
// atomic serialization: ~1.6M ops -> ~65K ops on d_EcD / d_mxD)
__global__ void k_cedges(const int* __restrict__ src, const int* __restrict__ dst){
    int e = blockIdx.x*blockDim.x + threadIdx.x;   // Ee divisible by 256: all lanes live
    int cs = d_cid[src[e]], cd = d_cid[dst[e]];
    bool win = false;
    float m = 0.f;
    if (cs != cd){
        int b = cs / Gn;
        int key = b*Gn*Gn + (cs - b*Gn)*Gn + (cd - b*Gn);
        unsigned bit = 1u << (key & 31);
        unsigned old = atomicOr(&d_markb[key >> 5], bit);
        if (!(old & bit)){
            win = true;
            float cx = d_pp[2*cs]   - d_pp[2*cd];
            float cy = d_pp[2*cs+1] - d_pp[2*cd+1];
            m = fmaxf(fabsf(cx), fabsf(cy));
        }
    }
    unsigned wmask = __ballot_sync(0xFFFFFFFFu, win);
    float wm = m;
    #pragma unroll
    for (int o = 16; o; o >>= 1) wm = fmaxf(wm, __shfl_xor_sync(0xFFFFFFFFu, wm, o));
    int lane = threadIdx.x & 31;
    int nwin = __popc(wmask);
    int base = 0;
    if (lane == 0 && nwin){
        base = atomicAdd(&d_EcD[0], nwin);
        atomicMax(&d_mxD[0], __float_as_uint(wm));
    }
    base = __shfl_sync(0xFFFFFFFFu, base, 0);
    if (win){
        int i = base + __popc(wmask & ((1u << lane) - 1));
        d_csrc[i] = cs; d_cdst[i] = cd;
        atomicAdd(&d_degc[cd], 1);
    }
}

__global__ void k_scatterC(){
    int i = blockIdx.x*blockDim.x + threadIdx.x;
    if (i >= d_EcD[0]) return;
    int cs = d_csrc[i], cd = d_cdst[i];
    int p = atomicAdd(&d_curc[cd], 1);
    float mx = __uint_as_float(d_mxD[0]);
    float den = 2.f*mx + 1e-12f;
    float f0 = (d_pp[2*cs]   - d_pp[2*cd])   / den + 0.5f;
    float f1 = (d_pp[2*cs+1] - d_pp[2*cd+1]) / den + 0.5f;
    f0 = fminf(fmaxf(f0, 0.f), 1.f);
    f1 = fminf(fmaxf(f1, 0.f), 1.f);
    d_ePc[p] = pack_edge(cs, (1.f-f0)*(1.f-f1), f0*(1.f-f1), (1.f-f0)*f1);
}

// ---------------- final: per-batch weighted mean (with BN fold) + FC ----------------
__global__ void k_final(const float* __restrict__ h, const float* __restrict__ fcW,
                        float* __restrict__ out){
    __shared__ float ss[8][33];
    __shared__ float sw8[8];
    __shared__ float gm[32];
    __shared__ float swv;
    int b = blockIdx.x;
    int lane = threadIdx.x & 31, w = threadIdx.x >> 5;
    float a7 = d_ssbL[7][lane], b7 = d_ssbL[7][32+lane];
    float acc = 0.f, accw = 0.f;
    for (int s = b*Gn + w; s < (b+1)*Gn; s += 8){
        float ww = d_wv[s];
        acc  += ww * (a7*h[(size_t)s*32 + lane] + b7);
        accw += ww;
    }
    ss[w][lane] = acc;
    if (lane == 0) sw8[w] = accw;
    __syncthreads();
    if (threadIdx.x < 32){
        float S = 0.f;
        #pragma unroll
        for (int j=0;j<8;j++) S += ss[j][threadIdx.x];
        gm[threadIdx.x] = S;
    }
    if (threadIdx.x == 0){
        float W = 0.f;
        #pragma unroll
        for (int j=0;j<8;j++) W += sw8[j];
        swv = W;
    }
    __syncthreads();
    if (threadIdx.x < 10){
        float o = 0.f;
        #pragma unroll
        for (int c=0;c<32;c++) o += (gm[c]/swv) * fcW[c*10 + threadIdx.x];
        out[b*10 + threadIdx.x] = o;
    }
}

// ---------------- host ----------------
template <typename T>
static T* devptr(const void* sym){
    void* p = nullptr;
    cudaGetSymbolAddress(&p, sym);
    return (T*)p;
}

extern "C" void kernel_launch(void* const* d_in, const int* in_sizes, int n_in,
                              void* d_out, int out_size){
    const float* x     = (const float*)d_in[0];
    const float* pos   = (const float*)d_in[1];
    const int*   batch = (const int*)  d_in[2];
    const int*   ei    = (const int*)  d_in[3];
    const int*   src   = ei;
    const int*   dst   = ei + Ee;
    const float* ea    = (const float*)d_in[4];
    const float* fcW   = (const float*)d_in[29];
    float* out = (float*)d_out;

    uint2*  pTh    = devptr<uint2>(d_Th);
    uint2*  pTch   = devptr<uint2>(d_Tch);
    float*  pU0    = devptr<float>(d_U0);
    float*  pU1    = devptr<float>(d_U1);
    float*  pU2    = devptr<float>(d_U2);
    int*    pdeg   = devptr<int>(d_deg);
    int*    prs    = devptr<int>(d_rs);
    int*    pcur   = devptr<int>(d_cur);
    uint2*  peP    = devptr<uint2>(d_eP);
    int*    pdegc  = devptr<int>(d_degc);
    int*    prsc   = devptr<int>(d_rsc);
    int*    pcurc  = devptr<int>(d_curc);
    uint2*  pePc   = devptr<uint2>(d_ePc);
    float*  pxp    = devptr<float>(d_xp);
    float*  pC0    = devptr<float>(d_C0);
    float*  pC1    = devptr<float>(d_C1);

    // prolog
    k_zeros<<<2048,256>>>();
    k_prep<<<Ee/256,256>>>(dst, pos, batch);
    k_scan1<<<256,1024>>>(pdeg, prs, Nn);
    k_scan2<<<1,256>>>(256);
    k_scan3<<<Nn/256,256>>>(pdeg, prs, pcur, Nn);
    k_scatter<<<Ee/256,256>>>(src, dst, ea);

    // fine layers
    k_xform<8><<<Nn/32,256>>>(x, nullptr, (const float*)d_in[5], pTh, Nn, 10, -1, -1);
    k_convF<8><<<Nn/32,256>>>(pTh, prs, peP, pU0, 0, Nn);
    k_bnstats<<<1,256>>>((const float*)d_in[6], (const float*)d_in[7], 0, 8, (float)Nn, 0);

    k_xform<16><<<Nn/16,256>>>(pU0, nullptr, (const float*)d_in[8], pTh, Nn, 8, 0, -1);
    k_convF<16><<<Nn/16,256>>>(pTh, prs, peP, pU1, 1, Nn);
    k_bnstats<<<1,256>>>((const float*)d_in[9], (const float*)d_in[10], 1, 16, (float)Nn, 0);

    k_xform<16><<<Nn/16,256>>>(pU1, nullptr, (const float*)d_in[11], pTh, Nn, 16, 1, -1);
    k_convF<16><<<Nn/16,256>>>(pTh, prs, peP, pU2, 2, Nn);
    k_bnstats<<<1,256>>>((const float*)d_in[12], (const float*)d_in[13], 2, 16, (float)Nn, 0);

    k_xform<16><<<Nn/16,256>>>(pU2, nullptr, (const float*)d_in[14], pTh, Nn, 16, 2, -1);
    k_convF<16><<<Nn/16,256>>>(pTh, prs, peP, pU0, 3, Nn);
    k_bnstats<<<1,256>>>((const float*)d_in[15], (const float*)d_in[16], 3, 16, (float)Nn, 0);

    k_xform<16><<<Nn/16,256>>>(pU0, nullptr, (const float*)d_in[17], pTh, Nn, 16, 3, -1);
    k_convF<16><<<Nn/16,256>>>(pTh, prs, peP, pU1, 4, Nn);
    k_bnstats<<<1,256>>>((const float*)d_in[18], (const float*)d_in[19], 4, 16, (float)Nn, 0);

    k_xform<32><<<Nn/8,256>>>(pU1, pU2, (const float*)d_in[20], pTh, Nn, 16, 4, 2);
    k_convF<32><<<Nn/8,256>>>(pTh, prs, peP, pU0, 5, Nn);
    k_bnstats<<<1,256>>>((const float*)d_in[21], (const float*)d_in[22], 5, 32, (float)Nn, 0);

    // pooling + coarse graph build
    k_poolmax<<<(Nn*32)/256,256>>>(pU0);
    k_cellfin<<<(Sn*32+255)/256,256>>>();
    k_cedges<<<Ee/256,256>>>(src, dst);
    k_scan1<<<(Sn+1023)/1024,1024>>>(pdegc, prsc, Sn);
    k_scan2<<<1,256>>>((Sn+1023)/1024);
    k_scan3<<<(Sn+255)/256,256>>>(pdegc, prsc, pcurc, Sn);
    k_scatterC<<<Ee/256,256>>>();

    // coarse layers (weighted BN)
    k_xform<32><<<(Sn+7)/8,256>>>(pxp, nullptr, (const float*)d_in[23], pTch, Sn, 32, -1, -1);
    k_convC<<<Sn,256>>>(pTch, prsc, pePc, pC0, 6);
    k_bnstats<<<1,256>>>((const float*)d_in[24], (const float*)d_in[25], 6, 32, 0.f, 1);

    k_xform<32><<<(Sn+7)/8,256>>>(pC0, nullptr, (const float*)d_in[26], pTch, Sn, 32, 6, -1);
    k_convC<<<Sn,256>>>(pTch, prsc, pePc, pC1, 7);
    k_bnstats<<<1,256>>>((const float*)d_in[27], (const float*)d_in[28], 7, 32, 0.f, 1);

    k_final<<<Bn,256>>>(pC1, fcW, out);
    (void)in_sizes; (void)n_in; (void)out_size;
}